// round 13
// baseline (speedup 1.0000x reference)
#include <cuda_runtime.h>
#include <cuda_fp16.h>
#include <cstdint>

#define BATCH   16384
#define IN_DIM  4096
#define OUT_DIM 64
#define BM      64
#define XCH     32                 // x-cols per superchunk
#define KCH     96                 // feature halfs per superchunk
#define NCH2    (IN_DIM / XCH)     // 128 superchunks
#define NS      6                  // m16n8k16 k-steps per superchunk
#define THREADS 256

#define A_ROW_W  52                // words per A row: 48 data (96 halfs) + 4 pad
#define A_BUF_W  (BM * A_ROW_W)    // 3328 words
#define B_BUF_W  (NS * 4 * 32 * 4) // 3072 words
#define TBL_W    32                // LUT floats
#define SMEM_BYTES ((TBL_W + 2 * A_BUF_W + 3 * B_BUF_W) * 4)   // 63616 B

// Fragment-ordered fp16 weights, superchunk-major, pair-packed per warp-column:
// word w: reg=w&1, nl=(w>>1)&1, lane=(w>>2)&31, ntp=(w>>7)&3, s=(w>>9)%6, q=(w>>9)/6
// halfs: k_local = 16s + 2*(lane&3) + 8*reg + h ;  n = (ntp*2+nl)*8 + (lane>>2)
__device__ __align__(16) __half2 g_w2[NCH2 * B_BUF_W];

// Piecewise cubic coefficients: [region][B0:c3,c2,c1,c0 | B1:c3,c2,c1,c0]
// Derived by expanding the verified truncated-power basis per region.
__device__ const float g_tbl[TBL_W] = {
    //  region 0: x in [-1,-0.5)
    1.3333333333333333f,  4.0f,  4.0f,  1.3333333333333333f,
    0.0f,                 0.0f,  0.0f,  0.0f,
    //  region 1: x in [-0.5,0)
    -4.0f,               -4.0f,  0.0f,  0.6666666666666666f,
    1.3333333333333333f,  2.0f,  1.0f,  0.16666666666666666f,
    //  region 2: x in [0,0.5)
    4.0f,                -4.0f,  0.0f,  0.6666666666666666f,
    -4.666666666666667f,  2.0f,  1.0f,  0.16666666666666666f,
    //  region 3: x in [0.5,1]
    -1.3333333333333333f, 4.0f, -4.0f,  1.3333333333333333f,
    7.333333333333333f, -16.0f, 10.0f, -1.3333333333333333f,
};

__device__ __forceinline__ float tanh_fast(float v) {
    float o;
    asm("tanh.approx.f32 %0, %1;" : "=f"(o) : "f"(v));
    return o;
}

// LUT piecewise-Horner basis + tanh silu.
__device__ __forceinline__ void kan_feat_lut(const float* __restrict__ tbl, float xv,
                                             float& b0, float& b1, float& si) {
    float xc = fminf(fmaxf(xv, -1.0f), 1.0f);
    int r = __float2int_rz(fmaf(xc, 2.0f, 2.0f));
    r = min(r, 3);
    float4 cb0 = *(const float4*)(tbl + r * 8);
    float4 cb1 = *(const float4*)(tbl + r * 8 + 4);
    b0 = fmaf(fmaf(fmaf(cb0.x, xc, cb0.y), xc, cb0.z), xc, cb0.w);
    b1 = fmaf(fmaf(fmaf(cb1.x, xc, cb1.y), xc, cb1.z), xc, cb1.w);
    float xh = 0.5f * xv;
    si = fmaf(xh, tanh_fast(xh), xh);    // x*sigmoid(x) = 0.5x(1+tanh(x/2))
}

__global__ void prep_weights_kernel(const float* __restrict__ c,
                                    const float* __restrict__ ws,
                                    const float* __restrict__ wb) {
    int w = blockIdx.x * blockDim.x + threadIdx.x;
    if (w >= NCH2 * B_BUF_W) return;
    int reg  = w & 1;
    int nl   = (w >> 1) & 1;
    int lane = (w >> 2) & 31;
    int ntp  = (w >> 7) & 3;
    int sq   = w >> 9;
    int s    = sq % 6;
    int q    = sq / 6;
    int t = lane & 3, g = lane >> 2;
    int n = (ntp * 2 + nl) * 8 + g;
    float v[2];
#pragma unroll
    for (int h = 0; h < 2; h++) {
        int kl = 16 * s + 2 * t + 8 * reg + h;
        int kg = q * KCH + kl;
        int i  = kg / 3, f = kg - 3 * i;
        int ij = i * OUT_DIM + n;
        v[h] = (f == 0) ? c[ij * 2] * ws[ij]
             : (f == 1) ? c[ij * 2 + 1] * ws[ij]
                        : wb[ij];
    }
    g_w2[w] = __floats2half2_rn(v[0], v[1]);
}

__device__ __forceinline__ void mma_f16(float* cc, uint32_t a0, uint32_t a1,
                                        uint32_t a2, uint32_t a3,
                                        uint32_t b0, uint32_t b1) {
    asm volatile("mma.sync.aligned.m16n8k16.row.col.f32.f16.f16.f32 "
                 "{%0,%1,%2,%3}, {%4,%5,%6,%7}, {%8,%9}, {%0,%1,%2,%3};"
                 : "+f"(cc[0]), "+f"(cc[1]), "+f"(cc[2]), "+f"(cc[3])
                 : "r"(a0), "r"(a1), "r"(a2), "r"(a3), "r"(b0), "r"(b1));
}

__device__ __forceinline__ void ldmatrix_x4(uint32_t& a0, uint32_t& a1,
                                            uint32_t& a2, uint32_t& a3, uint32_t addr) {
    asm volatile("ldmatrix.sync.aligned.m8n8.x4.shared.b16 {%0,%1,%2,%3}, [%4];"
                 : "=r"(a0), "=r"(a1), "=r"(a2), "=r"(a3) : "r"(addr));
}

__device__ __forceinline__ void cp_async16(uint32_t dst, const void* src) {
    asm volatile("cp.async.cg.shared.global [%0], [%1], 16;"
                 :: "r"(dst), "l"(__cvta_generic_to_global(src)) : "memory");
}

__device__ __forceinline__ uint32_t smem_u32(const void* p) {
    uint32_t a;
    asm("{ .reg .u64 t; cvta.to.shared.u64 t, %1; cvt.u32.u64 %0, t; }" : "=r"(a) : "l"(p));
    return a;
}

// Features for 8 x-values (24 halfs) -> 3x STS.128.
__device__ __forceinline__ void write_feat8(const float* __restrict__ tbl,
                                            uint32_t* dst, const float* xv) {
    float fe[24];
#pragma unroll
    for (int u = 0; u < 8; u++)
        kan_feat_lut(tbl, xv[u], fe[3 * u], fe[3 * u + 1], fe[3 * u + 2]);
    uint32_t hw[12];
#pragma unroll
    for (int j = 0; j < 12; j++) {
        __half2 h = __floats2half2_rn(fe[2 * j], fe[2 * j + 1]);
        hw[j] = *(uint32_t*)&h;
    }
    ((uint4*)dst)[0] = make_uint4(hw[0], hw[1], hw[2], hw[3]);
    ((uint4*)dst)[1] = make_uint4(hw[4], hw[5], hw[6], hw[7]);
    ((uint4*)dst)[2] = make_uint4(hw[8], hw[9], hw[10], hw[11]);
}

__global__ __launch_bounds__(THREADS, 2)
void kan_main_kernel(const float* __restrict__ x, float* __restrict__ out) {
    extern __shared__ uint32_t smw[];
    float*    Tbl = (float*)smw;               // [32] coefficient LUT
    uint32_t* Asm = smw + TBL_W;               // [2][A_BUF_W]  row-major A
    uint32_t* Bsm = smw + TBL_W + 2 * A_BUF_W; // [3][B_BUF_W]

    const int tid  = threadIdx.x;
    const int lane = tid & 31;
    const int wid  = tid >> 5;
    const int wr   = wid & 1;                  // 2 row groups of 32
    const int wc   = wid >> 1;                 // 4 col groups of 16
    const int g    = lane >> 2;
    const int t    = lane & 3;

    if (tid < TBL_W) Tbl[tid] = g_tbl[tid];

    // feature-writer role: row frow, x-cols [8*q4, 8*q4+8)
    const int frow = tid >> 2;                 // 0..63
    const int q4   = tid & 3;
    const float* xrow = x + (size_t)(blockIdx.x * BM + frow) * IN_DIM + q4 * 8;

    const uint32_t lrow = wr * 32 + (lane & 15);
    const uint32_t lcol = (lane >> 4) * 4;
    const uint32_t AsAddr = smem_u32(Asm);
    const uint32_t BsAddr = smem_u32(Bsm);
    uint32_t* Afw = Asm + frow * A_ROW_W + q4 * 12;

    float cacc[2][2][4];
#pragma unroll
    for (int mt = 0; mt < 2; mt++)
#pragma unroll
        for (int nl = 0; nl < 2; nl++)
#pragma unroll
            for (int r = 0; r < 4; r++) cacc[mt][nl][r] = 0.0f;

    // ---- prologue: B(0), B(1) via cp.async ----
#pragma unroll
    for (int pc = 0; pc < 2; pc++) {
        const char* src = (const char*)g_w2 + (size_t)pc * B_BUF_W * 4 + tid * 16;
        uint32_t dst = BsAddr + pc * B_BUF_W * 4 + tid * 16;
#pragma unroll
        for (int i = 0; i < 3; i++)
            cp_async16(dst + i * 4096, src + i * 4096);
        asm volatile("cp.async.commit_group;" ::: "memory");
    }
    __syncthreads();   // LUT visible before any feature computation

    float xs[8];
    {   // features(0) -> A buf 0
        float4 v0 = *(const float4*)(xrow + 0);
        float4 v1 = *(const float4*)(xrow + 4);
        float xv[8] = {v0.x, v0.y, v0.z, v0.w, v1.x, v1.y, v1.z, v1.w};
        write_feat8(Tbl, Afw, xv);
        const float* nx = xrow + XCH;
        v0 = *(const float4*)(nx + 0);
        v1 = *(const float4*)(nx + 4);
        xs[0] = v0.x; xs[1] = v0.y; xs[2] = v0.z; xs[3] = v0.w;
        xs[4] = v1.x; xs[5] = v1.y; xs[6] = v1.z; xs[7] = v1.w;
    }

    for (int ch = 0; ch < NCH2; ch++) {
        const int b  = ch & 1;
        const int b3 = ch % 3;

        asm volatile("cp.async.wait_group 1;" ::: "memory");
        __syncthreads();   // publish features(ch) in A[b] and B(ch) in Bsm[b3]

        // issue B(ch+2) into buf (ch+2)%3 (its last readers finished pre-barrier)
        {
            int nc = ch + 2 < NCH2 ? ch + 2 : NCH2 - 1;
            const char* src = (const char*)g_w2 + (size_t)nc * B_BUF_W * 4 + tid * 16;
            uint32_t dst = BsAddr + ((ch + 2) % 3) * B_BUF_W * 4 + tid * 16;
#pragma unroll
            for (int i = 0; i < 3; i++)
                cp_async16(dst + i * 4096, src + i * 4096);
            asm volatile("cp.async.commit_group;" ::: "memory");
        }

        // ---- MMA(ch): A[b] (ldmatrix) x B[b3] ----
        {
            const uint32_t abase = AsAddr + b * A_BUF_W * 4 + (lrow * A_ROW_W + lcol) * 4;
            const uint32_t* Bb = Bsm + b3 * B_BUF_W;
#pragma unroll
            for (int s = 0; s < NS; s++) {
                uint4 bv = *(const uint4*)(Bb + ((s * 4 + wc) * 32 + lane) * 4);
#pragma unroll
                for (int mt = 0; mt < 2; mt++) {
                    uint32_t a0, a1, a2, a3;
                    ldmatrix_x4(a0, a1, a2, a3, abase + mt * (16 * A_ROW_W * 4) + s * 32);
                    mma_f16(cacc[mt][0], a0, a1, a2, a3, bv.x, bv.y);
                    mma_f16(cacc[mt][1], a0, a1, a2, a3, bv.z, bv.w);
                }
            }
        }

        // ---- features(ch+1) -> A[b^1] (tail iterations write unused data) ----
        write_feat8(Tbl, Afw + (b ^ 1) * A_BUF_W, xs);

        // ---- stage x(ch+2) ----
        {
            int nc = ch + 2 < NCH2 ? ch + 2 : NCH2 - 1;
            const float* nx = xrow + (size_t)nc * XCH;
            float4 v0 = *(const float4*)(nx + 0);
            float4 v1 = *(const float4*)(nx + 4);
            xs[0] = v0.x; xs[1] = v0.y; xs[2] = v0.z; xs[3] = v0.w;
            xs[4] = v1.x; xs[5] = v1.y; xs[6] = v1.z; xs[7] = v1.w;
        }
    }

    // ---- epilogue ----
    const int row0 = blockIdx.x * BM + wr * 32 + g;
#pragma unroll
    for (int mt = 0; mt < 2; mt++) {
#pragma unroll
        for (int nl = 0; nl < 2; nl++) {
            int rA = row0 + mt * 16;
            int cA = (wc * 2 + nl) * 8 + 2 * t;
            *(float2*)(out + (size_t)rA * OUT_DIM + cA) =
                make_float2(cacc[mt][nl][0], cacc[mt][nl][1]);
            *(float2*)(out + (size_t)(rA + 8) * OUT_DIM + cA) =
                make_float2(cacc[mt][nl][2], cacc[mt][nl][3]);
        }
    }
}

extern "C" void kernel_launch(void* const* d_in, const int* in_sizes, int n_in,
                              void* d_out, int out_size) {
    const float* x  = (const float*)d_in[0];
    const float* c  = (const float*)d_in[1];
    const float* ws = (const float*)d_in[2];
    const float* wb = (const float*)d_in[3];
    float* out = (float*)d_out;

    cudaFuncSetAttribute(kan_main_kernel, cudaFuncAttributeMaxDynamicSharedMemorySize,
                         SMEM_BYTES);

    prep_weights_kernel<<<(NCH2 * B_BUF_W + 255) / 256, 256>>>(c, ws, wb);
    kan_main_kernel<<<BATCH / BM, THREADS, SMEM_BYTES>>>(x, out);
}

// round 14
// speedup vs baseline: 1.4150x; 1.4150x over previous
#include <cuda_runtime.h>
#include <cuda_fp16.h>
#include <cstdint>

#define BATCH   16384
#define IN_DIM  4096
#define OUT_DIM 64
#define BM      64
#define XCH     32                 // x-cols per superchunk
#define KCH     96                 // feature halfs per superchunk
#define NCH2    (IN_DIM / XCH)     // 128 superchunks
#define NS      6                  // m16n8k16 k-steps per superchunk
#define THREADS 256

#define A_ROW_W  52                // words per A row: 48 data (96 halfs) + 4 pad
#define A_BUF_W  (BM * A_ROW_W)    // 3328 words
#define B_BUF_W  (NS * 4 * 32 * 4) // 3072 words
#define SMEM_BYTES ((2 * A_BUF_W + 3 * B_BUF_W) * 4)   // 63488 B

// Fragment-ordered fp16 weights, superchunk-major, pair-packed per warp-column:
// word w: reg=w&1, nl=(w>>1)&1, lane=(w>>2)&31, ntp=(w>>7)&3, s=(w>>9)%6, q=(w>>9)/6
// halfs: k_local = 16s + 2*(lane&3) + 8*reg + h ;  n = (ntp*2+nl)*8 + (lane>>2)
__device__ __align__(16) __half2 g_w2[NCH2 * B_BUF_W];

__device__ __forceinline__ float tanh_fast(float v) {
    float o;
    asm("tanh.approx.f32 %0, %1;" : "=f"(o) : "f"(v));
    return o;
}

// Verified cubic B-spline basis (knots [-1,-.5,0,.5,1,(1)]) + silu(tanh form).
__device__ __forceinline__ void kan_features(float xv, float& b0, float& b1, float& si) {
    float xc = fminf(fmaxf(xv, -1.0f), 1.0f);
    float y1 = xc + 1.0f;
    float y2 = fmaxf(xc + 0.5f, 0.0f);
    float y3 = fmaxf(xc, 0.0f);
    float y4 = fmaxf(xc - 0.5f, 0.0f);
    float c1 = y1 * y1 * y1;
    float c2 = y2 * y2 * y2;
    float c3 = y3 * y3 * y3;
    float c4 = y4 * y4 * y4;
    const float k43  = 1.3333333333333333f;
    const float k163 = 5.3333333333333333f;
    b0 = fmaf(k43, c1, fmaf(-k163, c2, fmaf(8.0f, c3, -k163 * c4)));
    b1 = fmaf(k43, c2, fmaf(-6.0f, c3, 12.0f * c4));
    float xh = 0.5f * xv;
    si = fmaf(xh, tanh_fast(xh), xh);    // x*sigmoid(x) = 0.5x(1+tanh(x/2))
}

__global__ void prep_weights_kernel(const float* __restrict__ c,
                                    const float* __restrict__ ws,
                                    const float* __restrict__ wb) {
    int w = blockIdx.x * blockDim.x + threadIdx.x;
    if (w >= NCH2 * B_BUF_W) return;
    int reg  = w & 1;
    int nl   = (w >> 1) & 1;
    int lane = (w >> 2) & 31;
    int ntp  = (w >> 7) & 3;
    int sq   = w >> 9;
    int s    = sq % 6;
    int q    = sq / 6;
    int t = lane & 3, g = lane >> 2;
    int n = (ntp * 2 + nl) * 8 + g;
    float v[2];
#pragma unroll
    for (int h = 0; h < 2; h++) {
        int kl = 16 * s + 2 * t + 8 * reg + h;
        int kg = q * KCH + kl;
        int i  = kg / 3, f = kg - 3 * i;
        int ij = i * OUT_DIM + n;
        v[h] = (f == 0) ? c[ij * 2] * ws[ij]
             : (f == 1) ? c[ij * 2 + 1] * ws[ij]
                        : wb[ij];
    }
    g_w2[w] = __floats2half2_rn(v[0], v[1]);
}

__device__ __forceinline__ void mma_f16(float* cc, uint32_t a0, uint32_t a1,
                                        uint32_t a2, uint32_t a3,
                                        uint32_t b0, uint32_t b1) {
    asm volatile("mma.sync.aligned.m16n8k16.row.col.f32.f16.f16.f32 "
                 "{%0,%1,%2,%3}, {%4,%5,%6,%7}, {%8,%9}, {%0,%1,%2,%3};"
                 : "+f"(cc[0]), "+f"(cc[1]), "+f"(cc[2]), "+f"(cc[3])
                 : "r"(a0), "r"(a1), "r"(a2), "r"(a3), "r"(b0), "r"(b1));
}

__device__ __forceinline__ void ldmatrix_x4(uint32_t& a0, uint32_t& a1,
                                            uint32_t& a2, uint32_t& a3, uint32_t addr) {
    asm volatile("ldmatrix.sync.aligned.m8n8.x4.shared.b16 {%0,%1,%2,%3}, [%4];"
                 : "=r"(a0), "=r"(a1), "=r"(a2), "=r"(a3) : "r"(addr));
}

__device__ __forceinline__ void cp_async16(uint32_t dst, const void* src) {
    asm volatile("cp.async.cg.shared.global [%0], [%1], 16;"
                 :: "r"(dst), "l"(__cvta_generic_to_global(src)) : "memory");
}

__device__ __forceinline__ uint32_t smem_u32(const void* p) {
    uint32_t a;
    asm("{ .reg .u64 t; cvta.to.shared.u64 t, %1; cvt.u32.u64 %0, t; }" : "=r"(a) : "l"(p));
    return a;
}

// Features for 8 x-values (24 halfs) -> 3x STS.128 (same layout/banks as R7).
__device__ __forceinline__ void write_feat8(uint32_t* dst, const float* xv) {
    float fe[24];
#pragma unroll
    for (int u = 0; u < 8; u++)
        kan_features(xv[u], fe[3 * u], fe[3 * u + 1], fe[3 * u + 2]);
    uint32_t hw[12];
#pragma unroll
    for (int j = 0; j < 12; j++) {
        __half2 h = __floats2half2_rn(fe[2 * j], fe[2 * j + 1]);
        hw[j] = *(uint32_t*)&h;
    }
    ((uint4*)dst)[0] = make_uint4(hw[0], hw[1], hw[2], hw[3]);
    ((uint4*)dst)[1] = make_uint4(hw[4], hw[5], hw[6], hw[7]);
    ((uint4*)dst)[2] = make_uint4(hw[8], hw[9], hw[10], hw[11]);
}

__global__ __launch_bounds__(THREADS, 2)
void kan_main_kernel(const float* __restrict__ x, float* __restrict__ out) {
    extern __shared__ uint32_t smw[];
    uint32_t* Asm = smw;                       // [2][A_BUF_W]  row-major A
    uint32_t* Bsm = smw + 2 * A_BUF_W;         // [3][B_BUF_W]

    const int tid  = threadIdx.x;
    const int lane = tid & 31;
    const int wid  = tid >> 5;
    const bool isProd = (wid >= 4);

    // ---- consumer role (warps 0-3): 32x32 output tile each ----
    const int wr = wid & 1;                    // row group of 32
    const int wc = (wid >> 1) & 1;             // col group of 32
    const int g  = lane >> 2;
    const int t  = lane & 3;
    const uint32_t lrow = wr * 32 + (lane & 15);
    const uint32_t lcol = (lane >> 4) * 4;

    // ---- producer role (warps 4-7): rows r0 and r0+32, cols [8*q4, 8*q4+8) ----
    const int pid = tid & 127;
    const int r0  = pid >> 2;                  // 0..31
    const int q4  = pid & 3;
    const float* xrow0 = x + (size_t)(blockIdx.x * BM + r0) * IN_DIM + q4 * 8;
    const float* xrow1 = xrow0 + (size_t)32 * IN_DIM;

    const uint32_t AsAddr = smem_u32(Asm);
    const uint32_t BsAddr = smem_u32(Bsm);
    uint32_t* Afw0 = Asm + r0 * A_ROW_W + q4 * 12;
    uint32_t* Afw1 = Afw0 + 32 * A_ROW_W;

    float cacc[2][4][4];
#pragma unroll
    for (int mt = 0; mt < 2; mt++)
#pragma unroll
        for (int j = 0; j < 4; j++)
#pragma unroll
            for (int r = 0; r < 4; r++) cacc[mt][j][r] = 0.0f;

    // ---- prologue: B(0), B(1) via cp.async (all threads) ----
#pragma unroll
    for (int pc = 0; pc < 2; pc++) {
        const char* src = (const char*)g_w2 + (size_t)pc * B_BUF_W * 4 + tid * 16;
        uint32_t dst = BsAddr + pc * B_BUF_W * 4 + tid * 16;
#pragma unroll
        for (int i = 0; i < 3; i++)
            cp_async16(dst + i * 4096, src + i * 4096);
        asm volatile("cp.async.commit_group;" ::: "memory");
    }

    float xs[16];
    if (isProd) {   // features(0) -> A buf 0 ; stage x(1)
        float4 a0 = *(const float4*)(xrow0 + 0);
        float4 a1 = *(const float4*)(xrow0 + 4);
        float4 b0 = *(const float4*)(xrow1 + 0);
        float4 b1 = *(const float4*)(xrow1 + 4);
        float xv0[8] = {a0.x, a0.y, a0.z, a0.w, a1.x, a1.y, a1.z, a1.w};
        float xv1[8] = {b0.x, b0.y, b0.z, b0.w, b1.x, b1.y, b1.z, b1.w};
        write_feat8(Afw0, xv0);
        write_feat8(Afw1, xv1);
        a0 = *(const float4*)(xrow0 + XCH);     a1 = *(const float4*)(xrow0 + XCH + 4);
        b0 = *(const float4*)(xrow1 + XCH);     b1 = *(const float4*)(xrow1 + XCH + 4);
        xs[0]=a0.x; xs[1]=a0.y; xs[2]=a0.z; xs[3]=a0.w;
        xs[4]=a1.x; xs[5]=a1.y; xs[6]=a1.z; xs[7]=a1.w;
        xs[8]=b0.x; xs[9]=b0.y; xs[10]=b0.z; xs[11]=b0.w;
        xs[12]=b1.x; xs[13]=b1.y; xs[14]=b1.z; xs[15]=b1.w;
    }

    for (int ch = 0; ch < NCH2; ch++) {
        const int b  = ch & 1;
        const int b3 = ch % 3;

        asm volatile("cp.async.wait_group 1;" ::: "memory");
        __syncthreads();   // publish features(ch) in A[b] and B(ch) in Bsm[b3]

        // all threads: issue B(ch+2) into buf (ch+2)%3 (readers retired pre-barrier)
        {
            int nc = ch + 2 < NCH2 ? ch + 2 : NCH2 - 1;
            const char* src = (const char*)g_w2 + (size_t)nc * B_BUF_W * 4 + tid * 16;
            uint32_t dst = BsAddr + ((ch + 2) % 3) * B_BUF_W * 4 + tid * 16;
#pragma unroll
            for (int i = 0; i < 3; i++)
                cp_async16(dst + i * 4096, src + i * 4096);
            asm volatile("cp.async.commit_group;" ::: "memory");
        }

        if (!isProd) {
            // ---- consumers: MMA(ch): A[b] (ldmatrix) x B[b3], 32x32 per warp ----
            const uint32_t abase = AsAddr + b * A_BUF_W * 4 + (lrow * A_ROW_W + lcol) * 4;
            const uint32_t* Bb = Bsm + b3 * B_BUF_W;
#pragma unroll
            for (int s = 0; s < NS; s++) {
                uint4 bv0 = *(const uint4*)(Bb + ((s * 4 + wc * 2 + 0) * 32 + lane) * 4);
                uint4 bv1 = *(const uint4*)(Bb + ((s * 4 + wc * 2 + 1) * 32 + lane) * 4);
#pragma unroll
                for (int mt = 0; mt < 2; mt++) {
                    uint32_t a0, a1, a2, a3;
                    ldmatrix_x4(a0, a1, a2, a3, abase + mt * (16 * A_ROW_W * 4) + s * 32);
                    mma_f16(cacc[mt][0], a0, a1, a2, a3, bv0.x, bv0.y);
                    mma_f16(cacc[mt][1], a0, a1, a2, a3, bv0.z, bv0.w);
                    mma_f16(cacc[mt][2], a0, a1, a2, a3, bv1.x, bv1.y);
                    mma_f16(cacc[mt][3], a0, a1, a2, a3, bv1.z, bv1.w);
                }
            }
        } else {
            // ---- producers: features(ch+1) -> A[b^1]; stage x(ch+2) ----
            write_feat8(Afw0 + (b ^ 1) * A_BUF_W, xs + 0);
            write_feat8(Afw1 + (b ^ 1) * A_BUF_W, xs + 8);
            int nc = ch + 2 < NCH2 ? ch + 2 : NCH2 - 1;
            const float* n0 = xrow0 + (size_t)nc * XCH;
            const float* n1 = xrow1 + (size_t)nc * XCH;
            float4 a0 = *(const float4*)(n0 + 0);
            float4 a1 = *(const float4*)(n0 + 4);
            float4 b0 = *(const float4*)(n1 + 0);
            float4 b1 = *(const float4*)(n1 + 4);
            xs[0]=a0.x; xs[1]=a0.y; xs[2]=a0.z; xs[3]=a0.w;
            xs[4]=a1.x; xs[5]=a1.y; xs[6]=a1.z; xs[7]=a1.w;
            xs[8]=b0.x; xs[9]=b0.y; xs[10]=b0.z; xs[11]=b0.w;
            xs[12]=b1.x; xs[13]=b1.y; xs[14]=b1.z; xs[15]=b1.w;
        }
    }

    // ---- epilogue (consumers only) ----
    if (!isProd) {
        const int row0 = blockIdx.x * BM + wr * 32 + g;
#pragma unroll
        for (int mt = 0; mt < 2; mt++) {
#pragma unroll
            for (int j = 0; j < 4; j++) {
                int rA = row0 + mt * 16;
                int cA = wc * 32 + j * 8 + 2 * t;
                *(float2*)(out + (size_t)rA * OUT_DIM + cA) =
                    make_float2(cacc[mt][j][0], cacc[mt][j][1]);
                *(float2*)(out + (size_t)(rA + 8) * OUT_DIM + cA) =
                    make_float2(cacc[mt][j][2], cacc[mt][j][3]);
            }
        }
    }
}

extern "C" void kernel_launch(void* const* d_in, const int* in_sizes, int n_in,
                              void* d_out, int out_size) {
    const float* x  = (const float*)d_in[0];
    const float* c  = (const float*)d_in[1];
    const float* ws = (const float*)d_in[2];
    const float* wb = (const float*)d_in[3];
    float* out = (float*)d_out;

    cudaFuncSetAttribute(kan_main_kernel, cudaFuncAttributeMaxDynamicSharedMemorySize,
                         SMEM_BYTES);

    prep_weights_kernel<<<(NCH2 * B_BUF_W + 255) / 256, 256>>>(c, ws, wb);
    kan_main_kernel<<<BATCH / BM, THREADS, SMEM_BYTES>>>(x, out);
}

// round 15
// speedup vs baseline: 1.4630x; 1.0339x over previous
#include <cuda_runtime.h>
#include <cuda_fp16.h>
#include <cstdint>

#define BATCH   16384
#define IN_DIM  4096
#define OUT_DIM 64
#define BM      64
#define XCH     32                 // x-cols per superchunk
#define KCH     96                 // feature halfs per superchunk
#define NCH2    (IN_DIM / XCH)     // 128 superchunks
#define NS      6                  // m16n8k16 k-steps per superchunk
#define THREADS 256

#define A_ROW_W  52                // words per A row: 48 data (96 halfs) + 4 pad
#define A_BUF_W  (BM * A_ROW_W)    // 3328 words
#define B_BUF_W  (NS * 4 * 32 * 4) // 3072 words
#define SMEM_BYTES ((2 * A_BUF_W + 3 * B_BUF_W) * 4)   // 63488 B

// Fragment-ordered fp16 weights, superchunk-major, pair-packed per warp-column:
// word w: reg=w&1, nl=(w>>1)&1, lane=(w>>2)&31, ntp=(w>>7)&3, s=(w>>9)%6, q=(w>>9)/6
// halfs: k_local = 16s + 2*(lane&3) + 8*reg + h ;  n = (ntp*2+nl)*8 + (lane>>2)
__device__ __align__(16) __half2 g_w2[NCH2 * B_BUF_W];

__device__ __forceinline__ float tanh_fast(float v) {
    float o;
    asm("tanh.approx.f32 %0, %1;" : "=f"(o) : "f"(v));
    return o;
}

// Verified cubic B-spline basis (knots [-1,-.5,0,.5,1,(1)]) + silu(tanh form).
__device__ __forceinline__ void kan_features(float xv, float& b0, float& b1, float& si) {
    float xc = fminf(fmaxf(xv, -1.0f), 1.0f);
    float y1 = xc + 1.0f;
    float y2 = fmaxf(xc + 0.5f, 0.0f);
    float y3 = fmaxf(xc, 0.0f);
    float y4 = fmaxf(xc - 0.5f, 0.0f);
    float c1 = y1 * y1 * y1;
    float c2 = y2 * y2 * y2;
    float c3 = y3 * y3 * y3;
    float c4 = y4 * y4 * y4;
    const float k43  = 1.3333333333333333f;
    const float k163 = 5.3333333333333333f;
    b0 = fmaf(k43, c1, fmaf(-k163, c2, fmaf(8.0f, c3, -k163 * c4)));
    b1 = fmaf(k43, c2, fmaf(-6.0f, c3, 12.0f * c4));
    float xh = 0.5f * xv;
    si = fmaf(xh, tanh_fast(xh), xh);    // x*sigmoid(x) = 0.5x(1+tanh(x/2))
}

__global__ void prep_weights_kernel(const float* __restrict__ c,
                                    const float* __restrict__ ws,
                                    const float* __restrict__ wb) {
    int w = blockIdx.x * blockDim.x + threadIdx.x;
    if (w >= NCH2 * B_BUF_W) return;
    int reg  = w & 1;
    int nl   = (w >> 1) & 1;
    int lane = (w >> 2) & 31;
    int ntp  = (w >> 7) & 3;
    int sq   = w >> 9;
    int s    = sq % 6;
    int q    = sq / 6;
    int t = lane & 3, g = lane >> 2;
    int n = (ntp * 2 + nl) * 8 + g;
    float v[2];
#pragma unroll
    for (int h = 0; h < 2; h++) {
        int kl = 16 * s + 2 * t + 8 * reg + h;
        int kg = q * KCH + kl;
        int i  = kg / 3, f = kg - 3 * i;
        int ij = i * OUT_DIM + n;
        v[h] = (f == 0) ? c[ij * 2] * ws[ij]
             : (f == 1) ? c[ij * 2 + 1] * ws[ij]
                        : wb[ij];
    }
    g_w2[w] = __floats2half2_rn(v[0], v[1]);
}

__device__ __forceinline__ void mma_f16(float* cc, uint32_t a0, uint32_t a1,
                                        uint32_t a2, uint32_t a3,
                                        uint32_t b0, uint32_t b1) {
    asm volatile("mma.sync.aligned.m16n8k16.row.col.f32.f16.f16.f32 "
                 "{%0,%1,%2,%3}, {%4,%5,%6,%7}, {%8,%9}, {%0,%1,%2,%3};"
                 : "+f"(cc[0]), "+f"(cc[1]), "+f"(cc[2]), "+f"(cc[3])
                 : "r"(a0), "r"(a1), "r"(a2), "r"(a3), "r"(b0), "r"(b1));
}

__device__ __forceinline__ void ldmatrix_x4(uint32_t& a0, uint32_t& a1,
                                            uint32_t& a2, uint32_t& a3, uint32_t addr) {
    asm volatile("ldmatrix.sync.aligned.m8n8.x4.shared.b16 {%0,%1,%2,%3}, [%4];"
                 : "=r"(a0), "=r"(a1), "=r"(a2), "=r"(a3) : "r"(addr));
}

__device__ __forceinline__ void cp_async16(uint32_t dst, const void* src) {
    asm volatile("cp.async.cg.shared.global [%0], [%1], 16;"
                 :: "r"(dst), "l"(__cvta_generic_to_global(src)) : "memory");
}

__device__ __forceinline__ uint32_t smem_u32(const void* p) {
    uint32_t a;
    asm("{ .reg .u64 t; cvta.to.shared.u64 t, %1; cvt.u32.u64 %0, t; }" : "=r"(a) : "l"(p));
    return a;
}

// Features for 4 x-values (12 halfs = 6 words) -> 3x STS.64.
__device__ __forceinline__ void write_feat4(uint32_t* dst, float4 v) {
    float fe[12];
    kan_features(v.x, fe[0], fe[1], fe[2]);
    kan_features(v.y, fe[3], fe[4], fe[5]);
    kan_features(v.z, fe[6], fe[7], fe[8]);
    kan_features(v.w, fe[9], fe[10], fe[11]);
    uint32_t hw[6];
#pragma unroll
    for (int j = 0; j < 6; j++) {
        __half2 h = __floats2half2_rn(fe[2 * j], fe[2 * j + 1]);
        hw[j] = *(uint32_t*)&h;
    }
    ((uint2*)dst)[0] = make_uint2(hw[0], hw[1]);
    ((uint2*)dst)[1] = make_uint2(hw[2], hw[3]);
    ((uint2*)dst)[2] = make_uint2(hw[4], hw[5]);
}

__global__ __launch_bounds__(THREADS, 2)
void kan_main_kernel(const float* __restrict__ x, float* __restrict__ out) {
    extern __shared__ uint32_t smw[];
    uint32_t* Asm = smw;                       // [2][A_BUF_W]  row-major A
    uint32_t* Bsm = smw + 2 * A_BUF_W;         // [3][B_BUF_W]

    const int tid  = threadIdx.x;
    const int lane = tid & 31;
    const int wid  = tid >> 5;
    const bool isProd = (wid >= 4);

    // ---- consumer MMA role (warps 0-3): 32x32 output tile each ----
    const int wr = wid & 1;
    const int wc = (wid >> 1) & 1;
    const int g  = lane >> 2;
    const int t  = lane & 3;
    const uint32_t lrow = wr * 32 + (lane & 15);
    const uint32_t lcol = (lane >> 4) * 4;

    // ---- feature assignments ----
    // unit = (row, grp) ; grp covers x-cols [4*grp, 4*grp+4)
    // consumers (tid 0..127): 1 unit: row 48 + (tid>>3), grp tid&7
    // producers (tid 128..255): 3 units: rows p>>3, 16+(p>>3), 32+(p>>3), grp p&7
    const int fid  = tid & 127;
    const int fgrp = fid & 7;
    const int frow = isProd ? (fid >> 3) : (48 + (fid >> 3));
    const long xstep = (size_t)16 * IN_DIM;
    const float* xr0 = x + (size_t)(blockIdx.x * BM + frow) * IN_DIM + fgrp * 4;

    const uint32_t AsAddr = smem_u32(Asm);
    const uint32_t BsAddr = smem_u32(Bsm);
    uint32_t* Afw0 = Asm + frow * A_ROW_W + fgrp * 6;

    float cacc[2][4][4];
#pragma unroll
    for (int mt = 0; mt < 2; mt++)
#pragma unroll
        for (int j = 0; j < 4; j++)
#pragma unroll
            for (int r = 0; r < 4; r++) cacc[mt][j][r] = 0.0f;

    // ---- prologue: B(0), B(1) via cp.async (all threads) ----
#pragma unroll
    for (int pc = 0; pc < 2; pc++) {
        const char* src = (const char*)g_w2 + (size_t)pc * B_BUF_W * 4 + tid * 16;
        uint32_t dst = BsAddr + pc * B_BUF_W * 4 + tid * 16;
#pragma unroll
        for (int i = 0; i < 3; i++)
            cp_async16(dst + i * 4096, src + i * 4096);
        asm volatile("cp.async.commit_group;" ::: "memory");
    }

    // ---- features(0) + stage x(1) ----
    float4 xa[3];
    if (isProd) {
        write_feat4(Afw0,                 *(const float4*)(xr0));
        write_feat4(Afw0 + 16 * A_ROW_W,  *(const float4*)(xr0 + xstep));
        write_feat4(Afw0 + 32 * A_ROW_W,  *(const float4*)(xr0 + 2 * xstep));
        xa[0] = *(const float4*)(xr0 + XCH);
        xa[1] = *(const float4*)(xr0 + xstep + XCH);
        xa[2] = *(const float4*)(xr0 + 2 * xstep + XCH);
    } else {
        write_feat4(Afw0, *(const float4*)(xr0));
        xa[0] = *(const float4*)(xr0 + XCH);
    }

    for (int ch = 0; ch < NCH2; ch++) {
        const int b  = ch & 1;
        const int b3 = ch % 3;

        asm volatile("cp.async.wait_group 1;" ::: "memory");
        __syncthreads();   // publish features(ch) in A[b] and B(ch) in Bsm[b3]

        // all threads: issue B(ch+2) into buf (ch+2)%3 (readers retired pre-barrier)
        {
            int nc = ch + 2 < NCH2 ? ch + 2 : NCH2 - 1;
            const char* src = (const char*)g_w2 + (size_t)nc * B_BUF_W * 4 + tid * 16;
            uint32_t dst = BsAddr + ((ch + 2) % 3) * B_BUF_W * 4 + tid * 16;
#pragma unroll
            for (int i = 0; i < 3; i++)
                cp_async16(dst + i * 4096, src + i * 4096);
            asm volatile("cp.async.commit_group;" ::: "memory");
        }

        const int nc = ch + 2 < NCH2 ? ch + 2 : NCH2 - 1;
        uint32_t* Adst = Afw0 + (b ^ 1) * A_BUF_W;

        if (!isProd) {
            // ---- consumers: MMA(ch), then 1 feature unit for ch+1 ----
            const uint32_t abase = AsAddr + b * A_BUF_W * 4 + (lrow * A_ROW_W + lcol) * 4;
            const uint32_t* Bb = Bsm + b3 * B_BUF_W;
#pragma unroll
            for (int s = 0; s < NS; s++) {
                uint4 bv0 = *(const uint4*)(Bb + ((s * 4 + wc * 2 + 0) * 32 + lane) * 4);
                uint4 bv1 = *(const uint4*)(Bb + ((s * 4 + wc * 2 + 1) * 32 + lane) * 4);
#pragma unroll
                for (int mt = 0; mt < 2; mt++) {
                    uint32_t a0, a1, a2, a3;
                    ldmatrix_x4(a0, a1, a2, a3, abase + mt * (16 * A_ROW_W * 4) + s * 32);
                    mma_f16(cacc[mt][0], a0, a1, a2, a3, bv0.x, bv0.y);
                    mma_f16(cacc[mt][1], a0, a1, a2, a3, bv0.z, bv0.w);
                    mma_f16(cacc[mt][2], a0, a1, a2, a3, bv1.x, bv1.y);
                    mma_f16(cacc[mt][3], a0, a1, a2, a3, bv1.z, bv1.w);
                }
            }
            write_feat4(Adst, xa[0]);
            xa[0] = *(const float4*)(xr0 + (size_t)nc * XCH);
        } else {
            // ---- producers: 3 feature units for ch+1; stage x(ch+2) ----
            write_feat4(Adst,                xa[0]);
            write_feat4(Adst + 16 * A_ROW_W, xa[1]);
            write_feat4(Adst + 32 * A_ROW_W, xa[2]);
            xa[0] = *(const float4*)(xr0 + (size_t)nc * XCH);
            xa[1] = *(const float4*)(xr0 + xstep + (size_t)nc * XCH);
            xa[2] = *(const float4*)(xr0 + 2 * xstep + (size_t)nc * XCH);
        }
    }

    // ---- epilogue (consumers only) ----
    if (!isProd) {
        const int row0 = blockIdx.x * BM + wr * 32 + g;
#pragma unroll
        for (int mt = 0; mt < 2; mt++) {
#pragma unroll
            for (int j = 0; j < 4; j++) {
                int rA = row0 + mt * 16;
                int cA = wc * 32 + j * 8 + 2 * t;
                *(float2*)(out + (size_t)rA * OUT_DIM + cA) =
                    make_float2(cacc[mt][j][0], cacc[mt][j][1]);
                *(float2*)(out + (size_t)(rA + 8) * OUT_DIM + cA) =
                    make_float2(cacc[mt][j][2], cacc[mt][j][3]);
            }
        }
    }
}

extern "C" void kernel_launch(void* const* d_in, const int* in_sizes, int n_in,
                              void* d_out, int out_size) {
    const float* x  = (const float*)d_in[0];
    const float* c  = (const float*)d_in[1];
    const float* ws = (const float*)d_in[2];
    const float* wb = (const float*)d_in[3];
    float* out = (float*)d_out;

    cudaFuncSetAttribute(kan_main_kernel, cudaFuncAttributeMaxDynamicSharedMemorySize,
                         SMEM_BYTES);

    prep_weights_kernel<<<(NCH2 * B_BUF_W + 255) / 256, 256>>>(c, ws, wb);
    kan_main_kernel<<<BATCH / BM, THREADS, SMEM_BYTES>>>(x, out);
}

// round 16
// speedup vs baseline: 1.4951x; 1.0220x over previous
#include <cuda_runtime.h>
#include <cuda_fp16.h>
#include <cstdint>

#define BATCH   16384
#define IN_DIM  4096
#define OUT_DIM 64
#define BM      64
#define XCH     32                 // x-cols per superchunk
#define KCH     96                 // feature halfs per superchunk
#define NCH2    (IN_DIM / XCH)     // 128 superchunks
#define NS      6                  // m16n8k16 k-steps per superchunk
#define THREADS 256

#define A_ROW_W  52                // words per A row: 48 data (96 halfs) + 4 pad
#define A_BUF_W  (BM * A_ROW_W)    // 3328 words
#define B_BUF_W  (NS * 4 * 32 * 4) // 3072 words
#define SMEM_BYTES ((2 * A_BUF_W + 3 * B_BUF_W) * 4)   // 63488 B

// Fragment-ordered fp16 weights, superchunk-major, pair-packed per warp-column:
// word w: reg=w&1, nl=(w>>1)&1, lane=(w>>2)&31, ntp=(w>>7)&3, s=(w>>9)%6, q=(w>>9)/6
// halfs: k_local = 16s + 2*(lane&3) + 8*reg + h ;  n = (ntp*2+nl)*8 + (lane>>2)
__device__ __align__(16) __half2 g_w2[NCH2 * B_BUF_W];

__device__ __forceinline__ float tanh_fast(float v) {
    float o;
    asm("tanh.approx.f32 %0, %1;" : "=f"(o) : "f"(v));
    return o;
}

// Verified cubic B-spline basis (knots [-1,-.5,0,.5,1,(1)]) + silu(tanh form).
__device__ __forceinline__ void kan_features(float xv, float& b0, float& b1, float& si) {
    float xc = fminf(fmaxf(xv, -1.0f), 1.0f);
    float y1 = xc + 1.0f;
    float y2 = fmaxf(xc + 0.5f, 0.0f);
    float y3 = fmaxf(xc, 0.0f);
    float y4 = fmaxf(xc - 0.5f, 0.0f);
    float c1 = y1 * y1 * y1;
    float c2 = y2 * y2 * y2;
    float c3 = y3 * y3 * y3;
    float c4 = y4 * y4 * y4;
    const float k43  = 1.3333333333333333f;
    const float k163 = 5.3333333333333333f;
    b0 = fmaf(k43, c1, fmaf(-k163, c2, fmaf(8.0f, c3, -k163 * c4)));
    b1 = fmaf(k43, c2, fmaf(-6.0f, c3, 12.0f * c4));
    float xh = 0.5f * xv;
    si = fmaf(xh, tanh_fast(xh), xh);    // x*sigmoid(x) = 0.5x(1+tanh(x/2))
}

__global__ void prep_weights_kernel(const float* __restrict__ c,
                                    const float* __restrict__ ws,
                                    const float* __restrict__ wb) {
    int w = blockIdx.x * blockDim.x + threadIdx.x;
    if (w >= NCH2 * B_BUF_W) return;
    int reg  = w & 1;
    int nl   = (w >> 1) & 1;
    int lane = (w >> 2) & 31;
    int ntp  = (w >> 7) & 3;
    int sq   = w >> 9;
    int s    = sq % 6;
    int q    = sq / 6;
    int t = lane & 3, g = lane >> 2;
    int n = (ntp * 2 + nl) * 8 + g;
    float v[2];
#pragma unroll
    for (int h = 0; h < 2; h++) {
        int kl = 16 * s + 2 * t + 8 * reg + h;
        int kg = q * KCH + kl;
        int i  = kg / 3, f = kg - 3 * i;
        int ij = i * OUT_DIM + n;
        v[h] = (f == 0) ? c[ij * 2] * ws[ij]
             : (f == 1) ? c[ij * 2 + 1] * ws[ij]
                        : wb[ij];
    }
    g_w2[w] = __floats2half2_rn(v[0], v[1]);
}

__device__ __forceinline__ void mma_f16(float* cc, uint32_t a0, uint32_t a1,
                                        uint32_t a2, uint32_t a3,
                                        uint32_t b0, uint32_t b1) {
    asm volatile("mma.sync.aligned.m16n8k16.row.col.f32.f16.f16.f32 "
                 "{%0,%1,%2,%3}, {%4,%5,%6,%7}, {%8,%9}, {%0,%1,%2,%3};"
                 : "+f"(cc[0]), "+f"(cc[1]), "+f"(cc[2]), "+f"(cc[3])
                 : "r"(a0), "r"(a1), "r"(a2), "r"(a3), "r"(b0), "r"(b1));
}

__device__ __forceinline__ void ldmatrix_x4(uint32_t& a0, uint32_t& a1,
                                            uint32_t& a2, uint32_t& a3, uint32_t addr) {
    asm volatile("ldmatrix.sync.aligned.m8n8.x4.shared.b16 {%0,%1,%2,%3}, [%4];"
                 : "=r"(a0), "=r"(a1), "=r"(a2), "=r"(a3) : "r"(addr));
}

__device__ __forceinline__ void cp_async16(uint32_t dst, const void* src) {
    asm volatile("cp.async.cg.shared.global [%0], [%1], 16;"
                 :: "r"(dst), "l"(__cvta_generic_to_global(src)) : "memory");
}

__device__ __forceinline__ uint32_t smem_u32(const void* p) {
    uint32_t a;
    asm("{ .reg .u64 t; cvta.to.shared.u64 t, %1; cvt.u32.u64 %0, t; }" : "=r"(a) : "l"(p));
    return a;
}

// Features for 2 x-values (6 halfs = 3 words) -> 3x STS.32.
__device__ __forceinline__ void write_feat2(uint32_t* dst, float2 v) {
    float b0a, b1a, sa, b0b, b1b, sb;
    kan_features(v.x, b0a, b1a, sa);
    kan_features(v.y, b0b, b1b, sb);
    __half2 h0 = __floats2half2_rn(b0a, b1a);
    __half2 h1 = __floats2half2_rn(sa, b0b);
    __half2 h2 = __floats2half2_rn(b1b, sb);
    dst[0] = *(uint32_t*)&h0;
    dst[1] = *(uint32_t*)&h1;
    dst[2] = *(uint32_t*)&h2;
}

__global__ __launch_bounds__(THREADS, 2)
void kan_main_kernel(const float* __restrict__ x, float* __restrict__ out) {
    extern __shared__ uint32_t smw[];
    uint32_t* Asm = smw;                       // [2][A_BUF_W]  row-major A
    uint32_t* Bsm = smw + 2 * A_BUF_W;         // [3][B_BUF_W]

    const int tid  = threadIdx.x;
    const int lane = tid & 31;
    const int wid  = tid >> 5;
    const bool isProd = (wid >= 4);

    // ---- consumer MMA role (warps 0-3): 32x32 output tile each ----
    const int wr = wid & 1;
    const int wc = (wid >> 1) & 1;
    const int g  = lane >> 2;
    const int t  = lane & 3;
    const uint32_t lrow = wr * 32 + (lane & 15);
    const uint32_t lcol = (lane >> 4) * 4;

    // ---- feature role: 2-eval units (row, hg), hg covers x-cols [2hg, 2hg+2).
    // consumers: 3 units at rows R0, R0+8, R0+16  (R0 = fid>>4, rows 0..23)
    // producers: 5 units at rows 24+R0'+8k, k=0..4 (rows 24..63)
    const int fid = tid & 127;
    const int hg  = fid & 15;
    const int R0  = (isProd ? 24 : 0) + (fid >> 4);
    const float* xbase = x + (size_t)(blockIdx.x * BM + R0) * IN_DIM + 2 * hg;
    const size_t rstep = (size_t)8 * IN_DIM;

    const uint32_t AsAddr = smem_u32(Asm);
    const uint32_t BsAddr = smem_u32(Bsm);
    uint32_t* Afw = Asm + R0 * A_ROW_W + 3 * hg;

    float cacc[2][4][4];
#pragma unroll
    for (int mt = 0; mt < 2; mt++)
#pragma unroll
        for (int j = 0; j < 4; j++)
#pragma unroll
            for (int r = 0; r < 4; r++) cacc[mt][j][r] = 0.0f;

    // ---- prologue: B(0), B(1) via cp.async (all threads) ----
#pragma unroll
    for (int pc = 0; pc < 2; pc++) {
        const char* src = (const char*)g_w2 + (size_t)pc * B_BUF_W * 4 + tid * 16;
        uint32_t dst = BsAddr + pc * B_BUF_W * 4 + tid * 16;
#pragma unroll
        for (int i = 0; i < 3; i++)
            cp_async16(dst + i * 4096, src + i * 4096);
        asm volatile("cp.async.commit_group;" ::: "memory");
    }

    // ---- features(0) + stage x(1) ----
    float2 xa[5];
    if (isProd) {
#pragma unroll
        for (int k = 0; k < 5; k++)
            write_feat2(Afw + k * 8 * A_ROW_W, *(const float2*)(xbase + k * rstep));
#pragma unroll
        for (int k = 0; k < 5; k++)
            xa[k] = *(const float2*)(xbase + k * rstep + XCH);
    } else {
#pragma unroll
        for (int k = 0; k < 3; k++)
            write_feat2(Afw + k * 8 * A_ROW_W, *(const float2*)(xbase + k * rstep));
#pragma unroll
        for (int k = 0; k < 3; k++)
            xa[k] = *(const float2*)(xbase + k * rstep + XCH);
    }

    for (int ch = 0; ch < NCH2; ch++) {
        const int b  = ch & 1;
        const int b3 = ch % 3;

        asm volatile("cp.async.wait_group 1;" ::: "memory");
        __syncthreads();   // publish features(ch) in A[b] and B(ch) in Bsm[b3]

        // all threads: issue B(ch+2) into buf (ch+2)%3 (readers retired pre-barrier)
        {
            int nc2 = ch + 2 < NCH2 ? ch + 2 : NCH2 - 1;
            const char* src = (const char*)g_w2 + (size_t)nc2 * B_BUF_W * 4 + tid * 16;
            uint32_t dst = BsAddr + ((ch + 2) % 3) * B_BUF_W * 4 + tid * 16;
#pragma unroll
            for (int i = 0; i < 3; i++)
                cp_async16(dst + i * 4096, src + i * 4096);
            asm volatile("cp.async.commit_group;" ::: "memory");
        }

        const int nc = ch + 2 < NCH2 ? ch + 2 : NCH2 - 1;
        uint32_t* Adst = Afw + (b ^ 1) * A_BUF_W;

        if (!isProd) {
            // ---- consumers: MMA(ch), then 3 feature units for ch+1 ----
            const uint32_t abase = AsAddr + b * A_BUF_W * 4 + (lrow * A_ROW_W + lcol) * 4;
            const uint32_t* Bb = Bsm + b3 * B_BUF_W;
#pragma unroll
            for (int s = 0; s < NS; s++) {
                uint4 bv0 = *(const uint4*)(Bb + ((s * 4 + wc * 2 + 0) * 32 + lane) * 4);
                uint4 bv1 = *(const uint4*)(Bb + ((s * 4 + wc * 2 + 1) * 32 + lane) * 4);
#pragma unroll
                for (int mt = 0; mt < 2; mt++) {
                    uint32_t a0, a1, a2, a3;
                    ldmatrix_x4(a0, a1, a2, a3, abase + mt * (16 * A_ROW_W * 4) + s * 32);
                    mma_f16(cacc[mt][0], a0, a1, a2, a3, bv0.x, bv0.y);
                    mma_f16(cacc[mt][1], a0, a1, a2, a3, bv0.z, bv0.w);
                    mma_f16(cacc[mt][2], a0, a1, a2, a3, bv1.x, bv1.y);
                    mma_f16(cacc[mt][3], a0, a1, a2, a3, bv1.z, bv1.w);
                }
            }
#pragma unroll
            for (int k = 0; k < 3; k++) {
                write_feat2(Adst + k * 8 * A_ROW_W, xa[k]);
                xa[k] = *(const float2*)(xbase + k * rstep + (size_t)nc * XCH);
            }
        } else {
            // ---- producers: 5 feature units for ch+1; stage x(ch+2) ----
#pragma unroll
            for (int k = 0; k < 5; k++) {
                write_feat2(Adst + k * 8 * A_ROW_W, xa[k]);
                xa[k] = *(const float2*)(xbase + k * rstep + (size_t)nc * XCH);
            }
        }
    }

    // ---- epilogue (consumers only) ----
    if (!isProd) {
        const int row0 = blockIdx.x * BM + wr * 32 + g;
#pragma unroll
        for (int mt = 0; mt < 2; mt++) {
#pragma unroll
            for (int j = 0; j < 4; j++) {
                int rA = row0 + mt * 16;
                int cA = wc * 32 + j * 8 + 2 * t;
                *(float2*)(out + (size_t)rA * OUT_DIM + cA) =
                    make_float2(cacc[mt][j][0], cacc[mt][j][1]);
                *(float2*)(out + (size_t)(rA + 8) * OUT_DIM + cA) =
                    make_float2(cacc[mt][j][2], cacc[mt][j][3]);
            }
        }
    }
}

extern "C" void kernel_launch(void* const* d_in, const int* in_sizes, int n_in,
                              void* d_out, int out_size) {
    const float* x  = (const float*)d_in[0];
    const float* c  = (const float*)d_in[1];
    const float* ws = (const float*)d_in[2];
    const float* wb = (const float*)d_in[3];
    float* out = (float*)d_out;

    cudaFuncSetAttribute(kan_main_kernel, cudaFuncAttributeMaxDynamicSharedMemorySize,
                         SMEM_BYTES);

    prep_weights_kernel<<<(NCH2 * B_BUF_W + 255) / 256, 256>>>(c, ws, wb);
    kan_main_kernel<<<BATCH / BM, THREADS, SMEM_BYTES>>>(x, out);
}